// round 1
// baseline (speedup 1.0000x reference)
#include <cuda_runtime.h>

#define B_  2
#define S_  2048
#define H_  768
#define NH_ 12
#define HD_ 64

// Scratch for Q/K/V in [B, NH, S, HD] layout (12 MB each).
__device__ float g_q[B_ * NH_ * S_ * HD_];
__device__ float g_k[B_ * NH_ * S_ * HD_];
__device__ float g_v[B_ * NH_ * S_ * HD_];

// ---------------------------------------------------------------------------
// QKV projection: Y = X @ W + b, written directly into [B,NH,S,HD] layout.
// Grid: (NH=12 n-tiles, 64 m-tiles, 3 matrices). Block: 256 thr, 64x64 tile,
// BK=16, 4x4 per thread. Xs stored transposed [k][m] with XOR-8 swizzle
// (conflict-free scatter stores, broadcast reads).
// ---------------------------------------------------------------------------
__global__ __launch_bounds__(256) void qkv_proj_kernel(
    const float* __restrict__ X,
    const float* __restrict__ Wq, const float* __restrict__ bq,
    const float* __restrict__ Wk, const float* __restrict__ bk,
    const float* __restrict__ Wv, const float* __restrict__ bv)
{
    const int which = blockIdx.z;
    const float* W    = (which == 0) ? Wq : (which == 1) ? Wk : Wv;
    const float* bias = (which == 0) ? bq : (which == 1) ? bk : bv;
    float*       G    = (which == 0) ? g_q : (which == 1) ? g_k : g_v;

    __shared__ float Xs[16][64];   // [k][m], swizzled
    __shared__ float Ws[16][64];   // [k][n]

    const int tid = threadIdx.x;
    const int tx = tid & 15, ty = tid >> 4;
    const int m0   = blockIdx.y * 64;
    const int head = blockIdx.x;          // N-tile == one head (HD==64)
    const int n0   = head * 64;

    // X tile loader: thread -> (row lr, 4 consecutive k at lk)
    const int lr  = tid >> 2;              // 0..63
    const int lk  = (tid & 3) * 4;         // 0,4,8,12
    const int lsw = lr ^ ((lk >> 2) << 3); // swizzled column
    // W tile loader: thread -> (k-row wk, 4 consecutive n at wn)
    const int wk = tid >> 4;               // 0..15
    const int wn = (tid & 15) * 4;

    float acc[4][4] = {};

    for (int kt = 0; kt < H_; kt += 16) {
        float4 xv = *(const float4*)(X + (size_t)(m0 + lr) * H_ + kt + lk);
        Xs[lk + 0][lsw] = xv.x;
        Xs[lk + 1][lsw] = xv.y;
        Xs[lk + 2][lsw] = xv.z;
        Xs[lk + 3][lsw] = xv.w;
        *(float4*)&Ws[wk][wn] =
            *(const float4*)(W + (size_t)(kt + wk) * H_ + n0 + wn);
        __syncthreads();

        #pragma unroll
        for (int kk = 0; kk < 16; kk++) {
            float a[4], b[4];
            *(float4*)a = *(const float4*)&Xs[kk][(ty * 4) ^ ((kk >> 2) << 3)];
            *(float4*)b = *(const float4*)&Ws[kk][tx * 4];
            #pragma unroll
            for (int i = 0; i < 4; i++)
                #pragma unroll
                for (int j = 0; j < 4; j++)
                    acc[i][j] = fmaf(a[i], b[j], acc[i][j]);
        }
        __syncthreads();
    }

    const int b     = m0 >> 11;               // tile never crosses batch
    const int sbase = (m0 & (S_ - 1)) + ty * 4;
    float4 bv4 = *(const float4*)(bias + n0 + tx * 4);
    #pragma unroll
    for (int i = 0; i < 4; i++) {
        float4 v;
        v.x = acc[i][0] + bv4.x;
        v.y = acc[i][1] + bv4.y;
        v.z = acc[i][2] + bv4.z;
        v.w = acc[i][3] + bv4.w;
        *(float4*)&G[(((size_t)(b * NH_ + head) * S_) + sbase + i) * HD_ + tx * 4] = v;
    }
}

// ---------------------------------------------------------------------------
// Flash attention: one block per (q-tile of 64, head, batch). Online softmax.
// Qt/KP hold transposed [d][row] tiles for outer-product microkernel; KP is
// reused as P^T [kv][q] (XOR swizzle) for the PV GEMM; Vs is [kv][d] with
// XOR-4 swizzle. 48 KB smem total.
// ---------------------------------------------------------------------------
__global__ __launch_bounds__(256) void attn_kernel(float* __restrict__ out)
{
    const int head = blockIdx.y, b = blockIdx.z;
    const int bh = b * NH_ + head;
    const float* Q = g_q + (size_t)bh * S_ * HD_;
    const float* K = g_k + (size_t)bh * S_ * HD_;
    const float* V = g_v + (size_t)bh * S_ * HD_;
    const int q0 = blockIdx.x * 64;

    __shared__ float Qt[64][64];   // [d][q], pre-scaled by 1/sqrt(HD)
    __shared__ float KP[64][64];   // K^T [d][kv]  ->  P^T [kv][q] (swizzled)
    __shared__ float Vs[64][64];   // [kv][d], swizzled

    const int tid = threadIdx.x;
    const int tx = tid & 15, ty = tid >> 4;
    const int r  = tid & 63;            // loader row
    const int c4 = (tid >> 6) * 16;     // loader d-base

    {   // load + transpose + scale Q tile once
        const float* qp = Q + (size_t)(q0 + r) * HD_ + c4;
        #pragma unroll
        for (int i = 0; i < 4; i++) {
            float4 v = *(const float4*)(qp + i * 4);
            int d = c4 + i * 4;
            Qt[d + 0][r] = v.x * 0.125f;
            Qt[d + 1][r] = v.y * 0.125f;
            Qt[d + 2][r] = v.z * 0.125f;
            Qt[d + 3][r] = v.w * 0.125f;
        }
    }

    float o[4][4] = {};
    float m[4], l[4];
    #pragma unroll
    for (int i = 0; i < 4; i++) { m[i] = -1e30f; l[i] = 0.0f; }

    for (int kt = 0; kt < S_; kt += 64) {
        __syncthreads();   // prior PV reads of KP/Vs done (covers Qt 1st iter)
        {
            const float* kp = K + (size_t)(kt + r) * HD_ + c4;
            const float* vp = V + (size_t)(kt + r) * HD_ + c4;
            const int vsw = (r & 7) << 2;
            #pragma unroll
            for (int i = 0; i < 4; i++) {
                int d = c4 + i * 4;
                float4 kv4 = *(const float4*)(kp + i * 4);
                KP[d + 0][r] = kv4.x;   // transpose scatter: conflict-free
                KP[d + 1][r] = kv4.y;
                KP[d + 2][r] = kv4.z;
                KP[d + 3][r] = kv4.w;
                *(float4*)&Vs[r][d ^ vsw] = *(const float4*)(vp + i * 4);
            }
        }
        __syncthreads();

        // S = (Q*scale) @ K^T  (outer product over d)
        float s[4][4] = {};
        #pragma unroll
        for (int d = 0; d < 64; d++) {
            float a[4], bb[4];
            *(float4*)a  = *(const float4*)&Qt[d][ty * 4];
            *(float4*)bb = *(const float4*)&KP[d][tx * 4];
            #pragma unroll
            for (int i = 0; i < 4; i++)
                #pragma unroll
                for (int j = 0; j < 4; j++)
                    s[i][j] = fmaf(a[i], bb[j], s[i][j]);
        }

        // online softmax; row spread over 16 lanes (tx), reduce via shfl/16
        float mt[4];
        #pragma unroll
        for (int i = 0; i < 4; i++)
            mt[i] = fmaxf(fmaxf(s[i][0], s[i][1]), fmaxf(s[i][2], s[i][3]));
        #pragma unroll
        for (int off = 1; off < 16; off <<= 1)
            #pragma unroll
            for (int i = 0; i < 4; i++)
                mt[i] = fmaxf(mt[i], __shfl_xor_sync(0xffffffffu, mt[i], off, 16));

        float corr[4], lt[4];
        #pragma unroll
        for (int i = 0; i < 4; i++) {
            float mn = fmaxf(m[i], mt[i]);
            corr[i] = __expf(m[i] - mn);
            m[i] = mn;
            float sum = 0.0f;
            #pragma unroll
            for (int j = 0; j < 4; j++) {
                s[i][j] = __expf(s[i][j] - mn);
                sum += s[i][j];
            }
            lt[i] = sum;
        }
        #pragma unroll
        for (int off = 1; off < 16; off <<= 1)
            #pragma unroll
            for (int i = 0; i < 4; i++)
                lt[i] += __shfl_xor_sync(0xffffffffu, lt[i], off, 16);
        #pragma unroll
        for (int i = 0; i < 4; i++) {
            l[i] = l[i] * corr[i] + lt[i];
            #pragma unroll
            for (int j = 0; j < 4; j++)
                o[i][j] *= corr[i];
        }

        __syncthreads();   // everyone done reading KP as K^T
        // store P^T [kv][q], swizzled so the 4 float4 stores spread all banks
        #pragma unroll
        for (int j = 0; j < 4; j++) {
            int kv = tx * 4 + j;
            float4 pv = make_float4(s[0][j], s[1][j], s[2][j], s[3][j]);
            *(float4*)&KP[kv][(ty * 4) ^ (kv & 28)] = pv;
        }
        __syncthreads();

        // O += P @ V  (outer product over kv)
        #pragma unroll
        for (int kv = 0; kv < 64; kv++) {
            float a[4], bb[4];
            *(float4*)a  = *(const float4*)&KP[kv][(ty * 4) ^ (kv & 28)];
            *(float4*)bb = *(const float4*)&Vs[kv][(tx * 4) ^ ((kv & 7) << 2)];
            #pragma unroll
            for (int i = 0; i < 4; i++)
                #pragma unroll
                for (int j = 0; j < 4; j++)
                    o[i][j] = fmaf(a[i], bb[j], o[i][j]);
        }
    }

    // epilogue: normalize and merge heads -> out[b, s, h*HD + d]
    #pragma unroll
    for (int i = 0; i < 4; i++) {
        float inv = 1.0f / l[i];
        float4 v = make_float4(o[i][0] * inv, o[i][1] * inv,
                               o[i][2] * inv, o[i][3] * inv);
        *(float4*)&out[((size_t)(b * S_ + q0 + ty * 4 + i)) * H_
                       + head * HD_ + tx * 4] = v;
    }
}

// ---------------------------------------------------------------------------
extern "C" void kernel_launch(void* const* d_in, const int* in_sizes, int n_in,
                              void* d_out, int out_size)
{
    (void)in_sizes; (void)n_in; (void)out_size;
    const float* X  = (const float*)d_in[0];
    const float* Wq = (const float*)d_in[1];
    const float* bq = (const float*)d_in[2];
    const float* Wk = (const float*)d_in[3];
    const float* bk = (const float*)d_in[4];
    const float* Wv = (const float*)d_in[5];
    const float* bv = (const float*)d_in[6];
    float* out = (float*)d_out;

    qkv_proj_kernel<<<dim3(NH_, (B_ * S_) / 64, 3), 256>>>(X, Wq, bq, Wk, bk, Wv, bv);
    attn_kernel<<<dim3(S_ / 64, NH_, B_), 256>>>(out);
}

// round 4
// speedup vs baseline: 2.2072x; 2.2072x over previous
#include <cuda_runtime.h>
#include <cuda_bf16.h>
#include <cstdint>

#define B_  2
#define S_  2048
#define H_  768
#define NH_ 12
#define HD_ 64

// Packed hi/lo bf16 projections: [bh][s][128] (cols 0-63 = hi, 64-127 = lo).
// Q is pre-scaled by log2(e)/8 so attention scores are already in log2 domain.
__device__ __align__(16) __nv_bfloat16 g_qp[(size_t)B_ * NH_ * S_ * 128];
__device__ __align__(16) __nv_bfloat16 g_kp[(size_t)B_ * NH_ * S_ * 128];
__device__ __align__(16) __nv_bfloat16 g_vp[(size_t)B_ * NH_ * S_ * 128];

// ============================ PTX helpers ==================================
__device__ __forceinline__ uint32_t smem_u32(const void* p) {
    uint32_t a;
    asm("{ .reg .u64 t; cvta.to.shared.u64 t, %1; cvt.u32.u64 %0, t; }"
        : "=r"(a) : "l"(p));
    return a;
}
__device__ __forceinline__ void cpasync16(uint32_t dst, const void* src) {
    asm volatile("cp.async.cg.shared.global [%0], [%1], 16;"
                 :: "r"(dst), "l"(src) : "memory");
}
#define CP_COMMIT() asm volatile("cp.async.commit_group;" ::: "memory")
#define CP_WAIT0()  asm volatile("cp.async.wait_group 0;" ::: "memory")

__device__ __forceinline__ void ldsm4(uint32_t r[4], uint32_t addr) {
    asm volatile("ldmatrix.sync.aligned.m8n8.x4.shared.b16 {%0,%1,%2,%3}, [%4];"
        : "=r"(r[0]), "=r"(r[1]), "=r"(r[2]), "=r"(r[3]) : "r"(addr));
}
__device__ __forceinline__ void ldsm4t(uint32_t r[4], uint32_t addr) {
    asm volatile("ldmatrix.sync.aligned.m8n8.x4.trans.shared.b16 {%0,%1,%2,%3}, [%4];"
        : "=r"(r[0]), "=r"(r[1]), "=r"(r[2]), "=r"(r[3]) : "r"(addr));
}
__device__ __forceinline__ void mma16816(float c[4], const uint32_t a[4],
                                         uint32_t b0, uint32_t b1) {
    asm volatile("mma.sync.aligned.m16n8k16.row.col.f32.bf16.bf16.f32 "
        "{%0,%1,%2,%3}, {%4,%5,%6,%7}, {%8,%9}, {%0,%1,%2,%3};"
        : "+f"(c[0]), "+f"(c[1]), "+f"(c[2]), "+f"(c[3])
        : "r"(a[0]), "r"(a[1]), "r"(a[2]), "r"(a[3]), "r"(b0), "r"(b1));
}
__device__ __forceinline__ float ex2f(float x) {
    float y; asm("ex2.approx.f32 %0, %1;" : "=f"(y) : "f"(x)); return y;
}
// pack two fp32 -> bf16x2 (lo arg in bits [15:0], hi arg in bits [31:16])
__device__ __forceinline__ uint32_t packbf(float lo, float hi) {
    uint32_t r; asm("cvt.rn.bf16x2.f32 %0, %1, %2;" : "=r"(r) : "f"(hi), "f"(lo));
    return r;
}
// smem tile addressing: rows of 128 bf16 = 256B = 16 chunks of 16B,
// chunk XOR-swizzled by (row&7) -> conflict-free ldmatrix.
__device__ __forceinline__ uint32_t swa(int row, int chunk) {
    return (uint32_t)(row * 256 + ((chunk ^ (row & 7)) << 4));
}

// ---------------------------------------------------------------------------
// QKV projection (SIMT fp32 GEMM) -> packed hi/lo bf16 [bh][s][128].
// ---------------------------------------------------------------------------
__global__ __launch_bounds__(256) void qkv_proj_kernel(
    const float* __restrict__ X,
    const float* __restrict__ Wq, const float* __restrict__ bq,
    const float* __restrict__ Wk, const float* __restrict__ bk,
    const float* __restrict__ Wv, const float* __restrict__ bv)
{
    const int which = blockIdx.z;
    const float* W    = (which == 0) ? Wq : (which == 1) ? Wk : Wv;
    const float* bias = (which == 0) ? bq : (which == 1) ? bk : bv;
    __nv_bfloat16* Gp = (which == 0) ? g_qp : (which == 1) ? g_kp : g_vp;
    const float sc = (which == 0) ? 0.18033688011112042f : 1.0f;  // log2(e)/8

    __shared__ float Xs[16][64];
    __shared__ float Ws[16][64];

    const int tid = threadIdx.x;
    const int tx = tid & 15, ty = tid >> 4;
    const int m0   = blockIdx.y * 64;
    const int head = blockIdx.x;
    const int n0   = head * 64;

    const int lr  = tid >> 2;
    const int lk  = (tid & 3) * 4;
    const int lsw = lr ^ ((lk >> 2) << 3);
    const int wk = tid >> 4;
    const int wn = (tid & 15) * 4;

    float acc[4][4] = {};

    for (int kt = 0; kt < H_; kt += 16) {
        float4 xv = *(const float4*)(X + (size_t)(m0 + lr) * H_ + kt + lk);
        Xs[lk + 0][lsw] = xv.x;
        Xs[lk + 1][lsw] = xv.y;
        Xs[lk + 2][lsw] = xv.z;
        Xs[lk + 3][lsw] = xv.w;
        *(float4*)&Ws[wk][wn] =
            *(const float4*)(W + (size_t)(kt + wk) * H_ + n0 + wn);
        __syncthreads();

        #pragma unroll
        for (int kk = 0; kk < 16; kk++) {
            float a[4], b[4];
            *(float4*)a = *(const float4*)&Xs[kk][(ty * 4) ^ ((kk >> 2) << 3)];
            *(float4*)b = *(const float4*)&Ws[kk][tx * 4];
            #pragma unroll
            for (int i = 0; i < 4; i++)
                #pragma unroll
                for (int j = 0; j < 4; j++)
                    acc[i][j] = fmaf(a[i], b[j], acc[i][j]);
        }
        __syncthreads();
    }

    const int b     = m0 >> 11;
    const int bh    = b * NH_ + head;
    const int sbase = (m0 & (S_ - 1)) + ty * 4;
    float4 bv4 = *(const float4*)(bias + n0 + tx * 4);
    const float bb[4] = {bv4.x, bv4.y, bv4.z, bv4.w};

    #pragma unroll
    for (int i = 0; i < 4; i++) {
        unsigned short hs[4], ls[4];
        #pragma unroll
        for (int j = 0; j < 4; j++) {
            float y = (acc[i][j] + bb[j]) * sc;
            __nv_bfloat16 h = __float2bfloat16(y);
            float hf = __bfloat162float(h);
            __nv_bfloat16 l2 = __float2bfloat16(y - hf);
            hs[j] = __bfloat16_as_ushort(h);
            ls[j] = __bfloat16_as_ushort(l2);
        }
        uint2 hv = make_uint2((uint32_t)hs[0] | ((uint32_t)hs[1] << 16),
                              (uint32_t)hs[2] | ((uint32_t)hs[3] << 16));
        uint2 lv = make_uint2((uint32_t)ls[0] | ((uint32_t)ls[1] << 16),
                              (uint32_t)ls[2] | ((uint32_t)ls[3] << 16));
        size_t base = ((size_t)bh * S_ + sbase + i) * 128;
        *(uint2*)(Gp + base + tx * 4)      = hv;
        *(uint2*)(Gp + base + 64 + tx * 4) = lv;
    }
}

// ---------------------------------------------------------------------------
// HMMA flash attention, no-max softmax, bf16 hi/lo 3-pass (fp32-equivalent).
// Block: 128 thr (4 warps), q-tile 64 (16 rows/warp), kv-tile 128.
// smem: Q 16KB | K 32KB | V 32KB = 80KB; 2 CTAs/SM.
// ---------------------------------------------------------------------------
#define SMQ 0
#define SMK 16384
#define SMV 49152
#define SMTOT 81920

__global__ void __launch_bounds__(128, 2) attn_kernel(float* __restrict__ out)
{
    extern __shared__ char sm[];
    const uint32_t smb = smem_u32(sm);
    const uint32_t smq = smb + SMQ, smk = smb + SMK, smv = smb + SMV;

    const int tid = threadIdx.x;
    const int l = tid & 31, w = tid >> 5;
    const int head = blockIdx.y, b = blockIdx.z;
    const int bh = b * NH_ + head;
    const int q0 = blockIdx.x * 64;

    // --- async-load Q tile (64 rows x 16 chunks) ---
    {
        const __nv_bfloat16* Qg = g_qp + ((size_t)bh * S_ + q0) * 128;
        #pragma unroll
        for (int i = 0; i < 8; i++) {
            int idx = tid + 128 * i;
            int r = idx >> 4, ch = idx & 15;
            cpasync16(smq + swa(r, ch), Qg + (size_t)r * 128 + ch * 8);
        }
        CP_COMMIT();
    }

    float o[8][4];
    #pragma unroll
    for (int i = 0; i < 8; i++)
        #pragma unroll
        for (int j = 0; j < 4; j++) o[i][j] = 0.0f;
    float lsum0 = 0.0f, lsum1 = 0.0f;

    // fragment addressing constants
    const int arow  = (w << 4) + (l & 15);        // Q rows for A-frags
    const int achnk = l >> 4;                      // Q chunk half
    const int krow  = (l & 7) + ((l >> 4) << 3);   // K rows for B-frags
    const int kchnk = (l >> 3) & 1;                // K chunk half
    const int vchnk = l >> 4;                      // V chunk half

    const __nv_bfloat16* Kg0 = g_kp + (size_t)bh * S_ * 128;
    const __nv_bfloat16* Vg0 = g_vp + (size_t)bh * S_ * 128;

    for (int t = 0; t < S_ / 128; t++) {
        __syncthreads();   // previous tile fully consumed
        {
            const __nv_bfloat16* Kg = Kg0 + (size_t)t * 128 * 128;
            const __nv_bfloat16* Vg = Vg0 + (size_t)t * 128 * 128;
            #pragma unroll
            for (int i = 0; i < 16; i++) {
                int idx = tid + 128 * i;
                int r = idx >> 4, ch = idx & 15;
                uint32_t d = swa(r, ch);
                const size_t off = (size_t)r * 128 + ch * 8;
                cpasync16(smk + d, Kg + off);
                cpasync16(smv + d, Vg + off);
            }
        }
        CP_COMMIT();
        CP_WAIT0();
        __syncthreads();

        // ---- S = Qh.Kh + Qh.Kl + Ql.Kh  (16 ntiles of 8 kv, fp32 accum) ----
        float s[16][4];
        #pragma unroll
        for (int i = 0; i < 16; i++)
            #pragma unroll
            for (int j = 0; j < 4; j++) s[i][j] = 0.0f;

        #pragma unroll
        for (int pass = 0; pass < 3; pass++) {
            const int qc0 = (pass == 2) ? 8 : 0;   // Q-lo chunk base on pass 2
            const int kc0 = (pass == 1) ? 8 : 0;   // K-lo chunk base on pass 1
            #pragma unroll
            for (int ks = 0; ks < 4; ks++) {
                uint32_t a[4];
                ldsm4(a, smq + swa(arow, qc0 + ks * 2 + achnk));
                #pragma unroll
                for (int np = 0; np < 8; np++) {
                    uint32_t bb[4];
                    ldsm4(bb, smk + swa(np * 16 + krow, kc0 + ks * 2 + kchnk));
                    mma16816(s[2 * np],     a, bb[0], bb[1]);
                    mma16816(s[2 * np + 1], a, bb[2], bb[3]);
                }
            }
        }

        // ---- exp2 (scores already in log2 domain), sum, hi/lo split, PV ----
        #pragma unroll
        for (int c = 0; c < 8; c++) {          // kv 16-chunks
            uint32_t ah[4], al[4];
            #pragma unroll
            for (int h = 0; h < 2; h++) {      // the two kv ntiles of this chunk
                float* sp = s[2 * c + h];
                float p0 = ex2f(sp[0]), p1 = ex2f(sp[1]);
                float p2 = ex2f(sp[2]), p3 = ex2f(sp[3]);
                lsum0 += p0 + p1;
                lsum1 += p2 + p3;
                uint32_t h01 = packbf(p0, p1);
                uint32_t h23 = packbf(p2, p3);
                float r0 = p0 - __uint_as_float(h01 << 16);
                float r1 = p1 - __uint_as_float(h01 & 0xffff0000u);
                float r2 = p2 - __uint_as_float(h23 << 16);
                float r3 = p3 - __uint_as_float(h23 & 0xffff0000u);
                ah[2 * h]     = h01;
                ah[2 * h + 1] = h23;
                al[2 * h]     = packbf(r0, r1);
                al[2 * h + 1] = packbf(r2, r3);
            }
            const int vrow = c * 16 + (l & 15);
            uint32_t vh[4][4], vl[4][4];
            #pragma unroll
            for (int j = 0; j < 4; j++) {
                ldsm4t(vh[j], smv + swa(vrow, 2 * j + vchnk));       // V hi: chunks 0-7
                ldsm4t(vl[j], smv + swa(vrow, 8 + 2 * j + vchnk));   // V lo: chunks 8-15
            }
            #pragma unroll
            for (int j = 0; j < 4; j++) {   // Ph.Vh
                mma16816(o[2 * j],     ah, vh[j][0], vh[j][1]);
                mma16816(o[2 * j + 1], ah, vh[j][2], vh[j][3]);
            }
            #pragma unroll
            for (int j = 0; j < 4; j++) {   // Pl.Vh
                mma16816(o[2 * j],     al, vh[j][0], vh[j][1]);
                mma16816(o[2 * j + 1], al, vh[j][2], vh[j][3]);
            }
            #pragma unroll
            for (int j = 0; j < 4; j++) {   // Ph.Vl
                mma16816(o[2 * j],     ah, vl[j][0], vl[j][1]);
                mma16816(o[2 * j + 1], ah, vl[j][2], vl[j][3]);
            }
        }
    }

    // ---- epilogue: row-sum reduce across the 4 lanes of each row, write ----
    lsum0 += __shfl_xor_sync(0xffffffffu, lsum0, 1);
    lsum0 += __shfl_xor_sync(0xffffffffu, lsum0, 2);
    lsum1 += __shfl_xor_sync(0xffffffffu, lsum1, 1);
    lsum1 += __shfl_xor_sync(0xffffffffu, lsum1, 2);
    const float inv0 = 1.0f / lsum0;
    const float inv1 = 1.0f / lsum1;

    const int row0 = q0 + w * 16 + (l >> 2);
    const int row1 = row0 + 8;
    const int colb = head * HD_ + 2 * (l & 3);
    float* out0 = out + ((size_t)b * S_ + row0) * H_ + colb;
    float* out1 = out + ((size_t)b * S_ + row1) * H_ + colb;
    #pragma unroll
    for (int nt = 0; nt < 8; nt++) {
        *(float2*)(out0 + nt * 8) = make_float2(o[nt][0] * inv0, o[nt][1] * inv0);
        *(float2*)(out1 + nt * 8) = make_float2(o[nt][2] * inv1, o[nt][3] * inv1);
    }
}

// ---------------------------------------------------------------------------
extern "C" void kernel_launch(void* const* d_in, const int* in_sizes, int n_in,
                              void* d_out, int out_size)
{
    (void)in_sizes; (void)n_in; (void)out_size;
    const float* X  = (const float*)d_in[0];
    const float* Wq = (const float*)d_in[1];
    const float* bq = (const float*)d_in[2];
    const float* Wk = (const float*)d_in[3];
    const float* bk = (const float*)d_in[4];
    const float* Wv = (const float*)d_in[5];
    const float* bv = (const float*)d_in[6];
    float* out = (float*)d_out;

    cudaFuncSetAttribute(attn_kernel,
                         cudaFuncAttributeMaxDynamicSharedMemorySize, SMTOT);

    qkv_proj_kernel<<<dim3(NH_, (B_ * S_) / 64, 3), 256>>>(X, Wq, bq, Wk, bk, Wv, bv);
    attn_kernel<<<dim3(S_ / 64, NH_, B_), 128, SMTOT>>>(out);
}

// round 5
// speedup vs baseline: 3.8854x; 1.7604x over previous
#include <cuda_runtime.h>
#include <cuda_bf16.h>
#include <cstdint>

#define B_  2
#define S_  2048
#define H_  768
#define NH_ 12
#define HD_ 64
#define KB_ 12          // 768 / 64 k-chunks

// Packed hi/lo bf16 projections: [bh][s][128] (cols 0-63 = hi, 64-127 = lo).
// Q pre-scaled by log2(e)/8 so attention scores are already in log2 domain.
__device__ __align__(16) __nv_bfloat16 g_qp[(size_t)B_ * NH_ * S_ * 128];
__device__ __align__(16) __nv_bfloat16 g_kp[(size_t)B_ * NH_ * S_ * 128];
__device__ __align__(16) __nv_bfloat16 g_vp[(size_t)B_ * NH_ * S_ * 128];
// Packed hi/lo bf16 GEMM inputs:
// g_xb: [4096][12][128]  (per 64-k chunk: 64 hi | 64 lo)
// g_wb: [3][768 n][12][128]  (W transposed, per 64-k chunk: hi | lo)
__device__ __align__(16) __nv_bfloat16 g_xb[(size_t)B_ * S_ * KB_ * 128];
__device__ __align__(16) __nv_bfloat16 g_wb[(size_t)3 * H_ * KB_ * 128];

// ============================ PTX helpers ==================================
__device__ __forceinline__ uint32_t smem_u32(const void* p) {
    uint32_t a;
    asm("{ .reg .u64 t; cvta.to.shared.u64 t, %1; cvt.u32.u64 %0, t; }"
        : "=r"(a) : "l"(p));
    return a;
}
__device__ __forceinline__ void cpasync16(uint32_t dst, const void* src) {
    asm volatile("cp.async.cg.shared.global [%0], [%1], 16;"
                 :: "r"(dst), "l"(src) : "memory");
}
#define CP_COMMIT() asm volatile("cp.async.commit_group;" ::: "memory")
#define CP_WAIT0()  asm volatile("cp.async.wait_group 0;" ::: "memory")
#define CP_WAIT1()  asm volatile("cp.async.wait_group 1;" ::: "memory")

__device__ __forceinline__ void ldsm4(uint32_t r[4], uint32_t addr) {
    asm volatile("ldmatrix.sync.aligned.m8n8.x4.shared.b16 {%0,%1,%2,%3}, [%4];"
        : "=r"(r[0]), "=r"(r[1]), "=r"(r[2]), "=r"(r[3]) : "r"(addr));
}
__device__ __forceinline__ void ldsm4t(uint32_t r[4], uint32_t addr) {
    asm volatile("ldmatrix.sync.aligned.m8n8.x4.trans.shared.b16 {%0,%1,%2,%3}, [%4];"
        : "=r"(r[0]), "=r"(r[1]), "=r"(r[2]), "=r"(r[3]) : "r"(addr));
}
__device__ __forceinline__ void mma16816(float c[4], const uint32_t a[4],
                                         uint32_t b0, uint32_t b1) {
    asm volatile("mma.sync.aligned.m16n8k16.row.col.f32.bf16.bf16.f32 "
        "{%0,%1,%2,%3}, {%4,%5,%6,%7}, {%8,%9}, {%0,%1,%2,%3};"
        : "+f"(c[0]), "+f"(c[1]), "+f"(c[2]), "+f"(c[3])
        : "r"(a[0]), "r"(a[1]), "r"(a[2]), "r"(a[3]), "r"(b0), "r"(b1));
}
__device__ __forceinline__ float ex2f(float x) {
    float y; asm("ex2.approx.f32 %0, %1;" : "=f"(y) : "f"(x)); return y;
}
// pack two fp32 -> bf16x2 (first arg in bits [15:0], second in bits [31:16])
__device__ __forceinline__ uint32_t packbf(float lo, float hi) {
    uint32_t r; asm("cvt.rn.bf16x2.f32 %0, %1, %2;" : "=r"(r) : "f"(hi), "f"(lo));
    return r;
}
// smem tile addressing: rows of 128 bf16 = 256B = 16 chunks of 16B,
// chunk XOR-swizzled by (row&7) -> conflict-free ldmatrix.
__device__ __forceinline__ uint32_t swa(int row, int chunk) {
    return (uint32_t)(row * 256 + ((chunk ^ (row & 7)) << 4));
}

// ---------------------------------------------------------------------------
// conv_x: X fp32 [4096][768] -> g_xb packed hi/lo bf16 [m][kb][128].
// Thread handles 2 consecutive k of one row.
// ---------------------------------------------------------------------------
__global__ __launch_bounds__(256) void conv_x_kernel(const float* __restrict__ X)
{
    const int t = blockIdx.x * 256 + threadIdx.x;     // 4096*384 threads
    const int m = t / 384, r = t % 384;
    const int kb = r >> 5, pr = r & 31;
    float2 x = *(const float2*)(X + (size_t)m * H_ + kb * 64 + 2 * pr);
    uint32_t hi = packbf(x.x, x.y);
    float r0 = x.x - __uint_as_float(hi << 16);
    float r1 = x.y - __uint_as_float(hi & 0xffff0000u);
    uint32_t lo = packbf(r0, r1);
    uint32_t* dst = (uint32_t*)(g_xb + ((size_t)m * KB_ + kb) * 128);
    dst[pr]      = hi;
    dst[32 + pr] = lo;
}

// ---------------------------------------------------------------------------
// conv_w: W fp32 [768 k][768 n] -> g_wb packed hi/lo bf16 [which][n][kb][128]
// (transposed to n-major). One block per (kb, 64-n group, which); smem tile.
// ---------------------------------------------------------------------------
__global__ __launch_bounds__(256) void conv_w_kernel(
    const float* __restrict__ Wq, const float* __restrict__ Wk,
    const float* __restrict__ Wv)
{
    const int kb = blockIdx.x, ng = blockIdx.y, which = blockIdx.z;
    const float* W = (which == 0) ? Wq : (which == 1) ? Wk : Wv;

    __shared__ float T[64][65];
    const int tid = threadIdx.x;
    #pragma unroll
    for (int i = 0; i < 16; i++) {
        int idx = tid + 256 * i;
        int r = idx >> 6, c = idx & 63;      // r = k-local, c = n-local
        T[r][c] = W[(size_t)(kb * 64 + r) * H_ + ng * 64 + c];
    }
    __syncthreads();

    const int n  = tid >> 2;                  // 0..63
    const int jb = tid & 3;
    uint32_t* dst = (uint32_t*)(g_wb +
        (((size_t)which * H_ + ng * 64 + n) * KB_ + kb) * 128);
    #pragma unroll
    for (int j = 0; j < 8; j++) {
        int k2 = jb * 8 + j;
        float w0 = T[2 * k2][n], w1 = T[2 * k2 + 1][n];
        uint32_t hi = packbf(w0, w1);
        float r0 = w0 - __uint_as_float(hi << 16);
        float r1 = w1 - __uint_as_float(hi & 0xffff0000u);
        dst[k2]      = hi;
        dst[32 + k2] = packbf(r0, r1);
    }
}

// ---------------------------------------------------------------------------
// HMMA QKV GEMM: Y = X @ W + b (3-term bf16 hi/lo, fp32 accum), writing
// packed hi/lo bf16 into g_qp/g_kp/g_vp in attention layout.
// Block 256 thr (8 warps, 4m x 2n), tile 128m x 128n, K double-buffered
// in 64-chunks. smem 2 x (32KB A + 32KB B) = 128KB, 1 CTA/SM.
// ---------------------------------------------------------------------------
#define GSM_TOT 131072

__global__ void __launch_bounds__(256, 1) qkv_mma_kernel(
    const float* __restrict__ bq, const float* __restrict__ bk,
    const float* __restrict__ bv)
{
    extern __shared__ char sm[];
    const uint32_t smb = smem_u32(sm);

    const int tid = threadIdx.x;
    const int l = tid & 31, w = tid >> 5;
    const int wm = w & 3, wn = w >> 2;
    const int which = blockIdx.z;
    const int m0 = blockIdx.y * 128;
    const int n0 = blockIdx.x * 128;

    const __nv_bfloat16* Ag = g_xb + (size_t)m0 * KB_ * 128;
    const __nv_bfloat16* Bg = g_wb + ((size_t)which * H_ + n0) * KB_ * 128;

    // loader mapping: 2048 16B-chunks per tile / 256 thr = 8 each
    const int ldr = tid >> 1;                    // reused below per i
    (void)ldr;

    float s[2][8][4];
    #pragma unroll
    for (int mt = 0; mt < 2; mt++)
        #pragma unroll
        for (int nt = 0; nt < 8; nt++)
            #pragma unroll
            for (int j = 0; j < 4; j++) s[mt][nt][j] = 0.0f;

    // fragment lane constants (identical mapping to attention kernel)
    const int arow0 = 32 * wm + (l & 15);
    const int achnk = l >> 4;
    const int krow  = 64 * wn + (l & 7) + ((l >> 4) << 3);
    const int kchnk = (l >> 3) & 1;

    // prologue: load chunk 0 into buffer 0
    {
        #pragma unroll
        for (int i = 0; i < 8; i++) {
            int idx = tid + 256 * i;
            int r = idx >> 4, ch = idx & 15;
            uint32_t d = swa(r, ch);
            cpasync16(smb + d,         Ag + ((size_t)r * KB_) * 128 + ch * 8);
            cpasync16(smb + 32768 + d, Bg + ((size_t)r * KB_) * 128 + ch * 8);
        }
        CP_COMMIT();
    }

    for (int kb = 0; kb < KB_; kb++) {
        __syncthreads();   // all warps done with the buffer we're about to fill
        if (kb < KB_ - 1) {
            const uint32_t off = (uint32_t)(((kb + 1) & 1) * 65536);
            #pragma unroll
            for (int i = 0; i < 8; i++) {
                int idx = tid + 256 * i;
                int r = idx >> 4, ch = idx & 15;
                uint32_t d = swa(r, ch) + off;
                cpasync16(smb + d,         Ag + ((size_t)r * KB_ + kb + 1) * 128 + ch * 8);
                cpasync16(smb + 32768 + d, Bg + ((size_t)r * KB_ + kb + 1) * 128 + ch * 8);
            }
            CP_COMMIT();
            CP_WAIT1();
        } else {
            CP_WAIT0();
        }
        __syncthreads();

        const uint32_t smA = smb + (uint32_t)((kb & 1) * 65536);
        const uint32_t smB = smA + 32768;

        #pragma unroll
        for (int ks = 0; ks < 4; ks++) {
            uint32_t ah[2][4], al[2][4], bh[4][4], bl[4][4];
            #pragma unroll
            for (int mt = 0; mt < 2; mt++)
                ldsm4(ah[mt], smA + swa(arow0 + 16 * mt, ks * 2 + achnk));
            #pragma unroll
            for (int bt = 0; bt < 4; bt++)
                ldsm4(bh[bt], smB + swa(16 * bt + krow, ks * 2 + kchnk));
            #pragma unroll
            for (int mt = 0; mt < 2; mt++)
                #pragma unroll
                for (int bt = 0; bt < 4; bt++) {
                    mma16816(s[mt][2 * bt],     ah[mt], bh[bt][0], bh[bt][1]);
                    mma16816(s[mt][2 * bt + 1], ah[mt], bh[bt][2], bh[bt][3]);
                }
            #pragma unroll
            for (int bt = 0; bt < 4; bt++)
                ldsm4(bl[bt], smB + swa(16 * bt + krow, 8 + ks * 2 + kchnk));
            #pragma unroll
            for (int mt = 0; mt < 2; mt++)
                #pragma unroll
                for (int bt = 0; bt < 4; bt++) {
                    mma16816(s[mt][2 * bt],     ah[mt], bl[bt][0], bl[bt][1]);
                    mma16816(s[mt][2 * bt + 1], ah[mt], bl[bt][2], bl[bt][3]);
                }
            #pragma unroll
            for (int mt = 0; mt < 2; mt++)
                ldsm4(al[mt], smA + swa(arow0 + 16 * mt, 8 + ks * 2 + achnk));
            #pragma unroll
            for (int mt = 0; mt < 2; mt++)
                #pragma unroll
                for (int bt = 0; bt < 4; bt++) {
                    mma16816(s[mt][2 * bt],     al[mt], bh[bt][0], bh[bt][1]);
                    mma16816(s[mt][2 * bt + 1], al[mt], bh[bt][2], bh[bt][3]);
                }
        }
    }

    // ---- epilogue: +bias, (Q: *log2e/8), hi/lo split, packed store ----
    const float* bias = (which == 0) ? bq : (which == 1) ? bk : bv;
    __nv_bfloat16* Gp = (which == 0) ? g_qp : (which == 1) ? g_kp : g_vp;
    const float sc = (which == 0) ? 0.18033688011112042f : 1.0f;  // log2(e)/8

    const int head = 2 * blockIdx.x + wn;
    #pragma unroll
    for (int mt = 0; mt < 2; mt++) {
        const int r0 = m0 + 32 * wm + 16 * mt + (l >> 2);
        const int b  = r0 >> 11;
        const int s0 = r0 & (S_ - 1);
        const int bh_ = b * NH_ + head;
        uint32_t* d0 = (uint32_t*)(Gp + ((size_t)bh_ * S_ + s0) * 128);
        uint32_t* d1 = (uint32_t*)(Gp + ((size_t)bh_ * S_ + s0 + 8) * 128);
        #pragma unroll
        for (int nt = 0; nt < 8; nt++) {
            const int c0 = 8 * nt + 2 * (l & 3);
            const float b0 = __ldg(bias + head * 64 + c0);
            const float b1 = __ldg(bias + head * 64 + c0 + 1);
            float y00 = (s[mt][nt][0] + b0) * sc;
            float y01 = (s[mt][nt][1] + b1) * sc;
            float y10 = (s[mt][nt][2] + b0) * sc;
            float y11 = (s[mt][nt][3] + b1) * sc;
            uint32_t h0 = packbf(y00, y01);
            uint32_t h1 = packbf(y10, y11);
            uint32_t l0 = packbf(y00 - __uint_as_float(h0 << 16),
                                 y01 - __uint_as_float(h0 & 0xffff0000u));
            uint32_t l1 = packbf(y10 - __uint_as_float(h1 << 16),
                                 y11 - __uint_as_float(h1 & 0xffff0000u));
            d0[c0 >> 1]        = h0;
            d0[32 + (c0 >> 1)] = l0;
            d1[c0 >> 1]        = h1;
            d1[32 + (c0 >> 1)] = l1;
        }
    }
}

// ---------------------------------------------------------------------------
// HMMA flash attention, no-max softmax, bf16 hi/lo 3-pass (fp32-equivalent).
// Block: 128 thr (4 warps), q-tile 64 (16 rows/warp), kv-tile 128.
// smem: Q 16KB | K 32KB | V 32KB = 80KB; 2 CTAs/SM.
// ---------------------------------------------------------------------------
#define SMQ 0
#define SMK 16384
#define SMV 49152
#define SMTOT 81920

__global__ void __launch_bounds__(128, 2) attn_kernel(float* __restrict__ out)
{
    extern __shared__ char sm[];
    const uint32_t smb = smem_u32(sm);
    const uint32_t smq = smb + SMQ, smk = smb + SMK, smv = smb + SMV;

    const int tid = threadIdx.x;
    const int l = tid & 31, w = tid >> 5;
    const int head = blockIdx.y, b = blockIdx.z;
    const int bh = b * NH_ + head;
    const int q0 = blockIdx.x * 64;

    {
        const __nv_bfloat16* Qg = g_qp + ((size_t)bh * S_ + q0) * 128;
        #pragma unroll
        for (int i = 0; i < 8; i++) {
            int idx = tid + 128 * i;
            int r = idx >> 4, ch = idx & 15;
            cpasync16(smq + swa(r, ch), Qg + (size_t)r * 128 + ch * 8);
        }
        CP_COMMIT();
    }

    float o[8][4];
    #pragma unroll
    for (int i = 0; i < 8; i++)
        #pragma unroll
        for (int j = 0; j < 4; j++) o[i][j] = 0.0f;
    float lsum0 = 0.0f, lsum1 = 0.0f;

    const int arow  = (w << 4) + (l & 15);
    const int achnk = l >> 4;
    const int krow  = (l & 7) + ((l >> 4) << 3);
    const int kchnk = (l >> 3) & 1;
    const int vchnk = l >> 4;

    const __nv_bfloat16* Kg0 = g_kp + (size_t)bh * S_ * 128;
    const __nv_bfloat16* Vg0 = g_vp + (size_t)bh * S_ * 128;

    for (int t = 0; t < S_ / 128; t++) {
        __syncthreads();
        {
            const __nv_bfloat16* Kg = Kg0 + (size_t)t * 128 * 128;
            const __nv_bfloat16* Vg = Vg0 + (size_t)t * 128 * 128;
            #pragma unroll
            for (int i = 0; i < 16; i++) {
                int idx = tid + 128 * i;
                int r = idx >> 4, ch = idx & 15;
                uint32_t d = swa(r, ch);
                const size_t off = (size_t)r * 128 + ch * 8;
                cpasync16(smk + d, Kg + off);
                cpasync16(smv + d, Vg + off);
            }
        }
        CP_COMMIT();
        CP_WAIT0();
        __syncthreads();

        float s[16][4];
        #pragma unroll
        for (int i = 0; i < 16; i++)
            #pragma unroll
            for (int j = 0; j < 4; j++) s[i][j] = 0.0f;

        #pragma unroll
        for (int pass = 0; pass < 3; pass++) {
            const int qc0 = (pass == 2) ? 8 : 0;
            const int kc0 = (pass == 1) ? 8 : 0;
            #pragma unroll
            for (int ks = 0; ks < 4; ks++) {
                uint32_t a[4];
                ldsm4(a, smq + swa(arow, qc0 + ks * 2 + achnk));
                #pragma unroll
                for (int np = 0; np < 8; np++) {
                    uint32_t bb[4];
                    ldsm4(bb, smk + swa(np * 16 + krow, kc0 + ks * 2 + kchnk));
                    mma16816(s[2 * np],     a, bb[0], bb[1]);
                    mma16816(s[2 * np + 1], a, bb[2], bb[3]);
                }
            }
        }

        #pragma unroll
        for (int c = 0; c < 8; c++) {
            uint32_t ah[4], al[4];
            #pragma unroll
            for (int h = 0; h < 2; h++) {
                float* sp = s[2 * c + h];
                float p0 = ex2f(sp[0]), p1 = ex2f(sp[1]);
                float p2 = ex2f(sp[2]), p3 = ex2f(sp[3]);
                lsum0 += p0 + p1;
                lsum1 += p2 + p3;
                uint32_t h01 = packbf(p0, p1);
                uint32_t h23 = packbf(p2, p3);
                float r0 = p0 - __uint_as_float(h01 << 16);
                float r1 = p1 - __uint_as_float(h01 & 0xffff0000u);
                float r2 = p2 - __uint_as_float(h23 << 16);
                float r3 = p3 - __uint_as_float(h23 & 0xffff0000u);
                ah[2 * h]     = h01;
                ah[2 * h + 1] = h23;
                al[2 * h]     = packbf(r0, r1);
                al[2 * h + 1] = packbf(r2, r3);
            }
            const int vrow = c * 16 + (l & 15);
            uint32_t vh[4][4], vl[4][4];
            #pragma unroll
            for (int j = 0; j < 4; j++) {
                ldsm4t(vh[j], smv + swa(vrow, 2 * j + vchnk));
                ldsm4t(vl[j], smv + swa(vrow, 8 + 2 * j + vchnk));
            }
            #pragma unroll
            for (int j = 0; j < 4; j++) {
                mma16816(o[2 * j],     ah, vh[j][0], vh[j][1]);
                mma16816(o[2 * j + 1], ah, vh[j][2], vh[j][3]);
            }
            #pragma unroll
            for (int j = 0; j < 4; j++) {
                mma16816(o[2 * j],     al, vh[j][0], vh[j][1]);
                mma16816(o[2 * j + 1], al, vh[j][2], vh[j][3]);
            }
            #pragma unroll
            for (int j = 0; j < 4; j++) {
                mma16816(o[2 * j],     ah, vl[j][0], vl[j][1]);
                mma16816(o[2 * j + 1], ah, vl[j][2], vl[j][3]);
            }
        }
    }

    lsum0 += __shfl_xor_sync(0xffffffffu, lsum0, 1);
    lsum0 += __shfl_xor_sync(0xffffffffu, lsum0, 2);
    lsum1 += __shfl_xor_sync(0xffffffffu, lsum1, 1);
    lsum1 += __shfl_xor_sync(0xffffffffu, lsum1, 2);
    const float inv0 = 1.0f / lsum0;
    const float inv1 = 1.0f / lsum1;

    const int row0 = q0 + w * 16 + (l >> 2);
    const int row1 = row0 + 8;
    const int colb = head * HD_ + 2 * (l & 3);
    float* out0 = out + ((size_t)b * S_ + row0) * H_ + colb;
    float* out1 = out + ((size_t)b * S_ + row1) * H_ + colb;
    #pragma unroll
    for (int nt = 0; nt < 8; nt++) {
        *(float2*)(out0 + nt * 8) = make_float2(o[nt][0] * inv0, o[nt][1] * inv0);
        *(float2*)(out1 + nt * 8) = make_float2(o[nt][2] * inv1, o[nt][3] * inv1);
    }
}

// ---------------------------------------------------------------------------
extern "C" void kernel_launch(void* const* d_in, const int* in_sizes, int n_in,
                              void* d_out, int out_size)
{
    (void)in_sizes; (void)n_in; (void)out_size;
    const float* X  = (const float*)d_in[0];
    const float* Wq = (const float*)d_in[1];
    const float* bq = (const float*)d_in[2];
    const float* Wk = (const float*)d_in[3];
    const float* bk = (const float*)d_in[4];
    const float* Wv = (const float*)d_in[5];
    const float* bv = (const float*)d_in[6];
    float* out = (float*)d_out;

    cudaFuncSetAttribute(qkv_mma_kernel,
                         cudaFuncAttributeMaxDynamicSharedMemorySize, GSM_TOT);
    cudaFuncSetAttribute(attn_kernel,
                         cudaFuncAttributeMaxDynamicSharedMemorySize, SMTOT);

    conv_x_kernel<<<(B_ * S_ * 384) / 256, 256>>>(X);
    conv_w_kernel<<<dim3(KB_, H_ / 64, 3), 256>>>(Wq, Wk, Wv);
    qkv_mma_kernel<<<dim3(H_ / 128, (B_ * S_) / 128, 3), 256, GSM_TOT>>>(bq, bk, bv);
    attn_kernel<<<dim3(S_ / 64, NH_, B_), 128, SMTOT>>>(out);
}

// round 6
// speedup vs baseline: 4.0348x; 1.0385x over previous
#include <cuda_runtime.h>
#include <cuda_bf16.h>
#include <cstdint>

#define B_  2
#define S_  2048
#define H_  768
#define NH_ 12
#define HD_ 64
#define KB_ 12          // 768 / 64 k-chunks

// Packed hi/lo bf16 projections: [bh][s][128] (cols 0-63 = hi, 64-127 = lo).
// Q pre-scaled by log2(e)/8 so attention scores are already in log2 domain.
__device__ __align__(16) __nv_bfloat16 g_qp[(size_t)B_ * NH_ * S_ * 128];
__device__ __align__(16) __nv_bfloat16 g_kp[(size_t)B_ * NH_ * S_ * 128];
__device__ __align__(16) __nv_bfloat16 g_vp[(size_t)B_ * NH_ * S_ * 128];
// Packed hi/lo bf16 GEMM inputs:
// g_xb: [4096][12][128]  (per 64-k chunk: 64 hi | 64 lo)
// g_wb: [3][768 n][12][128]  (W transposed, per 64-k chunk: hi | lo)
__device__ __align__(16) __nv_bfloat16 g_xb[(size_t)B_ * S_ * KB_ * 128];
__device__ __align__(16) __nv_bfloat16 g_wb[(size_t)3 * H_ * KB_ * 128];

// ============================ PTX helpers ==================================
__device__ __forceinline__ uint32_t smem_u32(const void* p) {
    uint32_t a;
    asm("{ .reg .u64 t; cvta.to.shared.u64 t, %1; cvt.u32.u64 %0, t; }"
        : "=r"(a) : "l"(p));
    return a;
}
__device__ __forceinline__ void cpasync16(uint32_t dst, const void* src) {
    asm volatile("cp.async.cg.shared.global [%0], [%1], 16;"
                 :: "r"(dst), "l"(src) : "memory");
}
#define CP_COMMIT() asm volatile("cp.async.commit_group;" ::: "memory")
#define CP_WAIT0()  asm volatile("cp.async.wait_group 0;" ::: "memory")
#define CP_WAIT1()  asm volatile("cp.async.wait_group 1;" ::: "memory")
#define CP_WAIT2()  asm volatile("cp.async.wait_group 2;" ::: "memory")

__device__ __forceinline__ void ldsm4(uint32_t r[4], uint32_t addr) {
    asm volatile("ldmatrix.sync.aligned.m8n8.x4.shared.b16 {%0,%1,%2,%3}, [%4];"
        : "=r"(r[0]), "=r"(r[1]), "=r"(r[2]), "=r"(r[3]) : "r"(addr));
}
__device__ __forceinline__ void ldsm4t(uint32_t r[4], uint32_t addr) {
    asm volatile("ldmatrix.sync.aligned.m8n8.x4.trans.shared.b16 {%0,%1,%2,%3}, [%4];"
        : "=r"(r[0]), "=r"(r[1]), "=r"(r[2]), "=r"(r[3]) : "r"(addr));
}
__device__ __forceinline__ void mma16816(float c[4], const uint32_t a[4],
                                         uint32_t b0, uint32_t b1) {
    asm volatile("mma.sync.aligned.m16n8k16.row.col.f32.bf16.bf16.f32 "
        "{%0,%1,%2,%3}, {%4,%5,%6,%7}, {%8,%9}, {%0,%1,%2,%3};"
        : "+f"(c[0]), "+f"(c[1]), "+f"(c[2]), "+f"(c[3])
        : "r"(a[0]), "r"(a[1]), "r"(a[2]), "r"(a[3]), "r"(b0), "r"(b1));
}
__device__ __forceinline__ float ex2f(float x) {
    float y; asm("ex2.approx.f32 %0, %1;" : "=f"(y) : "f"(x)); return y;
}
// pack two fp32 -> bf16x2 (first arg in bits [15:0], second in bits [31:16])
__device__ __forceinline__ uint32_t packbf(float lo, float hi) {
    uint32_t r; asm("cvt.rn.bf16x2.f32 %0, %1, %2;" : "=r"(r) : "f"(hi), "f"(lo));
    return r;
}
// smem tile addressing: rows of 128 bf16 = 256B = 16 chunks of 16B,
// chunk XOR-swizzled by (row&7) -> conflict-free ldmatrix.
__device__ __forceinline__ uint32_t swa(int row, int chunk) {
    return (uint32_t)(row * 256 + ((chunk ^ (row & 7)) << 4));
}

// ---------------------------------------------------------------------------
// conv_x: X fp32 [4096][768] -> g_xb packed hi/lo bf16 [m][kb][128].
// ---------------------------------------------------------------------------
__global__ __launch_bounds__(256) void conv_x_kernel(const float* __restrict__ X)
{
    const int t = blockIdx.x * 256 + threadIdx.x;     // 4096*384 threads
    const int m = t / 384, r = t % 384;
    const int kb = r >> 5, pr = r & 31;
    float2 x = *(const float2*)(X + (size_t)m * H_ + kb * 64 + 2 * pr);
    uint32_t hi = packbf(x.x, x.y);
    float r0 = x.x - __uint_as_float(hi << 16);
    float r1 = x.y - __uint_as_float(hi & 0xffff0000u);
    uint32_t lo = packbf(r0, r1);
    uint32_t* dst = (uint32_t*)(g_xb + ((size_t)m * KB_ + kb) * 128);
    dst[pr]      = hi;
    dst[32 + pr] = lo;
}

// ---------------------------------------------------------------------------
// conv_w: W fp32 [768 k][768 n] -> g_wb packed hi/lo bf16 [which][n][kb][128]
// ---------------------------------------------------------------------------
__global__ __launch_bounds__(256) void conv_w_kernel(
    const float* __restrict__ Wq, const float* __restrict__ Wk,
    const float* __restrict__ Wv)
{
    const int kb = blockIdx.x, ng = blockIdx.y, which = blockIdx.z;
    const float* W = (which == 0) ? Wq : (which == 1) ? Wk : Wv;

    __shared__ float T[64][65];
    const int tid = threadIdx.x;
    #pragma unroll
    for (int i = 0; i < 16; i++) {
        int idx = tid + 256 * i;
        int r = idx >> 6, c = idx & 63;
        T[r][c] = W[(size_t)(kb * 64 + r) * H_ + ng * 64 + c];
    }
    __syncthreads();

    const int n  = tid >> 2;
    const int jb = tid & 3;
    uint32_t* dst = (uint32_t*)(g_wb +
        (((size_t)which * H_ + ng * 64 + n) * KB_ + kb) * 128);
    #pragma unroll
    for (int j = 0; j < 8; j++) {
        int k2 = jb * 8 + j;
        float w0 = T[2 * k2][n], w1 = T[2 * k2 + 1][n];
        uint32_t hi = packbf(w0, w1);
        float r0 = w0 - __uint_as_float(hi << 16);
        float r1 = w1 - __uint_as_float(hi & 0xffff0000u);
        dst[k2]      = hi;
        dst[32 + k2] = packbf(r0, r1);
    }
}

// ---------------------------------------------------------------------------
// HMMA QKV GEMM, triple-buffered (prefetch distance 2).
// smem 3 x (32KB A + 32KB B) = 192KB, 1 CTA/SM.
// ---------------------------------------------------------------------------
#define GSM_TOT 196608

__global__ void __launch_bounds__(256, 1) qkv_mma_kernel(
    const float* __restrict__ bq, const float* __restrict__ bk,
    const float* __restrict__ bv)
{
    extern __shared__ char sm[];
    const uint32_t smb = smem_u32(sm);

    const int tid = threadIdx.x;
    const int l = tid & 31, w = tid >> 5;
    const int wm = w & 3, wn = w >> 2;
    const int which = blockIdx.z;
    const int m0 = blockIdx.y * 128;
    const int n0 = blockIdx.x * 128;

    const __nv_bfloat16* Ag = g_xb + (size_t)m0 * KB_ * 128;
    const __nv_bfloat16* Bg = g_wb + ((size_t)which * H_ + n0) * KB_ * 128;

    float s[2][8][4];
    #pragma unroll
    for (int mt = 0; mt < 2; mt++)
        #pragma unroll
        for (int nt = 0; nt < 8; nt++)
            #pragma unroll
            for (int j = 0; j < 4; j++) s[mt][nt][j] = 0.0f;

    const int arow0 = 32 * wm + (l & 15);
    const int achnk = l >> 4;
    const int krow  = 64 * wn + (l & 7) + ((l >> 4) << 3);
    const int kchnk = (l >> 3) & 1;

    // prologue: chunks 0 and 1 into buffers 0 and 1
    #pragma unroll
    for (int pb = 0; pb < 2; pb++) {
        const uint32_t off = (uint32_t)(pb * 65536);
        #pragma unroll
        for (int i = 0; i < 8; i++) {
            int idx = tid + 256 * i;
            int r = idx >> 4, ch = idx & 15;
            uint32_t d = swa(r, ch) + off;
            cpasync16(smb + d,         Ag + ((size_t)r * KB_ + pb) * 128 + ch * 8);
            cpasync16(smb + 32768 + d, Bg + ((size_t)r * KB_ + pb) * 128 + ch * 8);
        }
        CP_COMMIT();
    }

    for (int kb = 0; kb < KB_; kb++) {
        CP_WAIT1();          // chunk kb complete (its group is >= 2nd-newest)
        __syncthreads();     // all warps past compute(kb-1); buffer (kb+2)%3 free
        if (kb + 2 < KB_) {
            const uint32_t off = (uint32_t)(((kb + 2) % 3) * 65536);
            #pragma unroll
            for (int i = 0; i < 8; i++) {
                int idx = tid + 256 * i;
                int r = idx >> 4, ch = idx & 15;
                uint32_t d = swa(r, ch) + off;
                cpasync16(smb + d,         Ag + ((size_t)r * KB_ + kb + 2) * 128 + ch * 8);
                cpasync16(smb + 32768 + d, Bg + ((size_t)r * KB_ + kb + 2) * 128 + ch * 8);
            }
        }
        CP_COMMIT();         // always commit (keeps group counting uniform)

        const uint32_t smA = smb + (uint32_t)((kb % 3) * 65536);
        const uint32_t smB = smA + 32768;

        #pragma unroll
        for (int ks = 0; ks < 4; ks++) {
            uint32_t ah[2][4], al[2][4], bh[4][4], bl[4][4];
            #pragma unroll
            for (int mt = 0; mt < 2; mt++)
                ldsm4(ah[mt], smA + swa(arow0 + 16 * mt, ks * 2 + achnk));
            #pragma unroll
            for (int bt = 0; bt < 4; bt++)
                ldsm4(bh[bt], smB + swa(16 * bt + krow, ks * 2 + kchnk));
            #pragma unroll
            for (int mt = 0; mt < 2; mt++)
                #pragma unroll
                for (int bt = 0; bt < 4; bt++) {
                    mma16816(s[mt][2 * bt],     ah[mt], bh[bt][0], bh[bt][1]);
                    mma16816(s[mt][2 * bt + 1], ah[mt], bh[bt][2], bh[bt][3]);
                }
            #pragma unroll
            for (int bt = 0; bt < 4; bt++)
                ldsm4(bl[bt], smB + swa(16 * bt + krow, 8 + ks * 2 + kchnk));
            #pragma unroll
            for (int mt = 0; mt < 2; mt++)
                #pragma unroll
                for (int bt = 0; bt < 4; bt++) {
                    mma16816(s[mt][2 * bt],     ah[mt], bl[bt][0], bl[bt][1]);
                    mma16816(s[mt][2 * bt + 1], ah[mt], bl[bt][2], bl[bt][3]);
                }
            #pragma unroll
            for (int mt = 0; mt < 2; mt++)
                ldsm4(al[mt], smA + swa(arow0 + 16 * mt, 8 + ks * 2 + achnk));
            #pragma unroll
            for (int mt = 0; mt < 2; mt++)
                #pragma unroll
                for (int bt = 0; bt < 4; bt++) {
                    mma16816(s[mt][2 * bt],     al[mt], bh[bt][0], bh[bt][1]);
                    mma16816(s[mt][2 * bt + 1], al[mt], bh[bt][2], bh[bt][3]);
                }
        }
    }

    // ---- epilogue: +bias, (Q: *log2e/8), hi/lo split, packed store ----
    const float* bias = (which == 0) ? bq : (which == 1) ? bk : bv;
    __nv_bfloat16* Gp = (which == 0) ? g_qp : (which == 1) ? g_kp : g_vp;
    const float sc = (which == 0) ? 0.18033688011112042f : 1.0f;

    const int head = 2 * blockIdx.x + wn;
    #pragma unroll
    for (int mt = 0; mt < 2; mt++) {
        const int r0 = m0 + 32 * wm + 16 * mt + (l >> 2);
        const int b  = r0 >> 11;
        const int s0 = r0 & (S_ - 1);
        const int bh_ = b * NH_ + head;
        uint32_t* d0 = (uint32_t*)(Gp + ((size_t)bh_ * S_ + s0) * 128);
        uint32_t* d1 = (uint32_t*)(Gp + ((size_t)bh_ * S_ + s0 + 8) * 128);
        #pragma unroll
        for (int nt = 0; nt < 8; nt++) {
            const int c0 = 8 * nt + 2 * (l & 3);
            const float b0 = __ldg(bias + head * 64 + c0);
            const float b1 = __ldg(bias + head * 64 + c0 + 1);
            float y00 = (s[mt][nt][0] + b0) * sc;
            float y01 = (s[mt][nt][1] + b1) * sc;
            float y10 = (s[mt][nt][2] + b0) * sc;
            float y11 = (s[mt][nt][3] + b1) * sc;
            uint32_t h0 = packbf(y00, y01);
            uint32_t h1 = packbf(y10, y11);
            uint32_t l0 = packbf(y00 - __uint_as_float(h0 << 16),
                                 y01 - __uint_as_float(h0 & 0xffff0000u));
            uint32_t l1 = packbf(y10 - __uint_as_float(h1 << 16),
                                 y11 - __uint_as_float(h1 & 0xffff0000u));
            d0[c0 >> 1]        = h0;
            d0[32 + (c0 >> 1)] = l0;
            d1[c0 >> 1]        = h1;
            d1[32 + (c0 >> 1)] = l1;
        }
    }
}

// ---------------------------------------------------------------------------
// HMMA flash attention: q-tile 64, kv-tile 64, triple-buffered K/V prefetch,
// Q fragments hoisted to registers. smem Q 16KB + 3x32KB = 112KB; 2 CTAs/SM.
// ---------------------------------------------------------------------------
#define SMQ   0
#define SMKV  16384
#define SMTOT 114688
#define NT_   (S_ / 64)

__global__ void __launch_bounds__(128, 2) attn_kernel(float* __restrict__ out)
{
    extern __shared__ char sm[];
    const uint32_t smb = smem_u32(sm);
    const uint32_t smq = smb + SMQ;

    const int tid = threadIdx.x;
    const int l = tid & 31, w = tid >> 5;
    const int head = blockIdx.y, b = blockIdx.z;
    const int bh = b * NH_ + head;
    const int q0 = blockIdx.x * 64;

    const __nv_bfloat16* Kg0 = g_kp + (size_t)bh * S_ * 128;
    const __nv_bfloat16* Vg0 = g_vp + (size_t)bh * S_ * 128;

    // --- prologue: Q, kv0, kv1 (three cp.async groups) ---
    {
        const __nv_bfloat16* Qg = g_qp + ((size_t)bh * S_ + q0) * 128;
        #pragma unroll
        for (int i = 0; i < 8; i++) {
            int idx = tid + 128 * i;
            int r = idx >> 4, ch = idx & 15;
            cpasync16(smq + swa(r, ch), Qg + (size_t)r * 128 + ch * 8);
        }
        CP_COMMIT();
    }
    #pragma unroll
    for (int pb = 0; pb < 2; pb++) {
        const uint32_t kvb = smb + SMKV + (uint32_t)(pb * 32768);
        const __nv_bfloat16* Kg = Kg0 + (size_t)pb * 64 * 128;
        const __nv_bfloat16* Vg = Vg0 + (size_t)pb * 64 * 128;
        #pragma unroll
        for (int i = 0; i < 8; i++) {
            int idx = tid + 128 * i;
            int r = idx >> 4, ch = idx & 15;
            uint32_t d = swa(r, ch);
            cpasync16(kvb + d,         Kg + (size_t)r * 128 + ch * 8);
            cpasync16(kvb + 16384 + d, Vg + (size_t)r * 128 + ch * 8);
        }
        CP_COMMIT();
    }

    // fragment lane constants
    const int arow  = (w << 4) + (l & 15);
    const int achnk = l >> 4;
    const int krow  = (l & 7) + ((l >> 4) << 3);
    const int kchnk = (l >> 3) & 1;
    const int vchnk = l >> 4;

    // --- hoist Q fragments (hi/lo) into registers; Q smem dead afterwards ---
    CP_WAIT2();          // Q group complete
    __syncthreads();
    uint32_t qf[2][4][4];
    #pragma unroll
    for (int hl = 0; hl < 2; hl++)
        #pragma unroll
        for (int ks = 0; ks < 4; ks++)
            ldsm4(qf[hl][ks], smq + swa(arow, hl * 8 + ks * 2 + achnk));

    float o[8][4];
    #pragma unroll
    for (int i = 0; i < 8; i++)
        #pragma unroll
        for (int j = 0; j < 4; j++) o[i][j] = 0.0f;
    float lsum0 = 0.0f, lsum1 = 0.0f;

    for (int t = 0; t < NT_; t++) {
        CP_WAIT1();      // kv tile t resident (its group is >= 2nd-newest)
        __syncthreads(); // all warps past compute(t-1); buffer (t+2)%3 free
        if (t + 2 < NT_) {
            const uint32_t kvb = smb + SMKV + (uint32_t)(((t + 2) % 3) * 32768);
            const __nv_bfloat16* Kg = Kg0 + (size_t)(t + 2) * 64 * 128;
            const __nv_bfloat16* Vg = Vg0 + (size_t)(t + 2) * 64 * 128;
            #pragma unroll
            for (int i = 0; i < 8; i++) {
                int idx = tid + 128 * i;
                int r = idx >> 4, ch = idx & 15;
                uint32_t d = swa(r, ch);
                cpasync16(kvb + d,         Kg + (size_t)r * 128 + ch * 8);
                cpasync16(kvb + 16384 + d, Vg + (size_t)r * 128 + ch * 8);
            }
        }
        CP_COMMIT();

        const uint32_t smk = smb + SMKV + (uint32_t)((t % 3) * 32768);
        const uint32_t smv = smk + 16384;

        // ---- S = Qh.Kh + Ql.Kh + Qh.Kl  (Kh loaded once, used twice) ----
        float s[8][4];
        #pragma unroll
        for (int i = 0; i < 8; i++)
            #pragma unroll
            for (int j = 0; j < 4; j++) s[i][j] = 0.0f;

        #pragma unroll
        for (int ks = 0; ks < 4; ks++) {
            #pragma unroll
            for (int np = 0; np < 4; np++) {
                uint32_t kh[4], kl[4];
                ldsm4(kh, smk + swa(np * 16 + krow, ks * 2 + kchnk));
                ldsm4(kl, smk + swa(np * 16 + krow, 8 + ks * 2 + kchnk));
                mma16816(s[2 * np],     qf[0][ks], kh[0], kh[1]);
                mma16816(s[2 * np + 1], qf[0][ks], kh[2], kh[3]);
                mma16816(s[2 * np],     qf[1][ks], kh[0], kh[1]);
                mma16816(s[2 * np + 1], qf[1][ks], kh[2], kh[3]);
                mma16816(s[2 * np],     qf[0][ks], kl[0], kl[1]);
                mma16816(s[2 * np + 1], qf[0][ks], kl[2], kl[3]);
            }
        }

        // ---- exp2, sum, hi/lo split, PV (3-pass) ----
        #pragma unroll
        for (int c = 0; c < 4; c++) {
            uint32_t ah[4], al[4];
            #pragma unroll
            for (int h = 0; h < 2; h++) {
                float* sp = s[2 * c + h];
                float p0 = ex2f(sp[0]), p1 = ex2f(sp[1]);
                float p2 = ex2f(sp[2]), p3 = ex2f(sp[3]);
                lsum0 += p0 + p1;
                lsum1 += p2 + p3;
                uint32_t h01 = packbf(p0, p1);
                uint32_t h23 = packbf(p2, p3);
                float r0 = p0 - __uint_as_float(h01 << 16);
                float r1 = p1 - __uint_as_float(h01 & 0xffff0000u);
                float r2 = p2 - __uint_as_float(h23 << 16);
                float r3 = p3 - __uint_as_float(h23 & 0xffff0000u);
                ah[2 * h]     = h01;
                ah[2 * h + 1] = h23;
                al[2 * h]     = packbf(r0, r1);
                al[2 * h + 1] = packbf(r2, r3);
            }
            const int vrow = c * 16 + (l & 15);
            uint32_t vh[4][4], vl[4][4];
            #pragma unroll
            for (int j = 0; j < 4; j++) {
                ldsm4t(vh[j], smv + swa(vrow, 2 * j + vchnk));
                ldsm4t(vl[j], smv + swa(vrow, 8 + 2 * j + vchnk));
            }
            #pragma unroll
            for (int j = 0; j < 4; j++) {
                mma16816(o[2 * j],     ah, vh[j][0], vh[j][1]);
                mma16816(o[2 * j + 1], ah, vh[j][2], vh[j][3]);
            }
            #pragma unroll
            for (int j = 0; j < 4; j++) {
                mma16816(o[2 * j],     al, vh[j][0], vh[j][1]);
                mma16816(o[2 * j + 1], al, vh[j][2], vh[j][3]);
            }
            #pragma unroll
            for (int j = 0; j < 4; j++) {
                mma16816(o[2 * j],     ah, vl[j][0], vl[j][1]);
                mma16816(o[2 * j + 1], ah, vl[j][2], vl[j][3]);
            }
        }
    }

    // ---- epilogue ----
    lsum0 += __shfl_xor_sync(0xffffffffu, lsum0, 1);
    lsum0 += __shfl_xor_sync(0xffffffffu, lsum0, 2);
    lsum1 += __shfl_xor_sync(0xffffffffu, lsum1, 1);
    lsum1 += __shfl_xor_sync(0xffffffffu, lsum1, 2);
    const float inv0 = 1.0f / lsum0;
    const float inv1 = 1.0f / lsum1;

    const int row0 = q0 + w * 16 + (l >> 2);
    const int row1 = row0 + 8;
    const int colb = head * HD_ + 2 * (l & 3);
    float* out0 = out + ((size_t)b * S_ + row0) * H_ + colb;
    float* out1 = out + ((size_t)b * S_ + row1) * H_ + colb;
    #pragma unroll
    for (int nt = 0; nt < 8; nt++) {
        *(float2*)(out0 + nt * 8) = make_float2(o[nt][0] * inv0, o[nt][1] * inv0);
        *(float2*)(out1 + nt * 8) = make_float2(o[nt][2] * inv1, o[nt][3] * inv1);
    }
}

// ---------------------------------------------------------------------------
extern "C" void kernel_launch(void* const* d_in, const int* in_sizes, int n_in,
                              void* d_out, int out_size)
{
    (void)in_sizes; (void)n_in; (void)out_size;
    const float* X  = (const float*)d_in[0];
    const float* Wq = (const float*)d_in[1];
    const float* bq = (const float*)d_in[2];
    const float* Wk = (const float*)d_in[3];
    const float* bk = (const float*)d_in[4];
    const float* Wv = (const float*)d_in[5];
    const float* bv = (const float*)d_in[6];
    float* out = (float*)d_out;

    cudaFuncSetAttribute(qkv_mma_kernel,
                         cudaFuncAttributeMaxDynamicSharedMemorySize, GSM_TOT);
    cudaFuncSetAttribute(attn_kernel,
                         cudaFuncAttributeMaxDynamicSharedMemorySize, SMTOT);

    conv_x_kernel<<<(B_ * S_ * 384) / 256, 256>>>(X);
    conv_w_kernel<<<dim3(KB_, H_ / 64, 3), 256>>>(Wq, Wk, Wv);
    qkv_mma_kernel<<<dim3(H_ / 128, (B_ * S_) / 128, 3), 256, GSM_TOT>>>(bq, bk, bv);
    attn_kernel<<<dim3(S_ / 64, NH_, B_), 128, SMTOT>>>(out);
}